// round 16
// baseline (speedup 1.0000x reference)
#include <cuda_runtime.h>
#include <cuda_bf16.h>
#include <math.h>
#include <stdint.h>

#define B_ 64
#define T_ 1024
#define E_ 512
#define H_ 256
#define M_ (B_*T_)          // 65536

// RNN constants (proven best layout, ~1012us/launch)
#define WREG2 48
#define WSH4  8
#define HSTRIDE 132
#define HBUF   264

// ---------------- scratch (device globals; no allocation allowed) ----------------
__device__ float g_xp[(size_t)2*T_*B_*H_];     // per-layer projections [2][T][B][H]
__device__ float g_x2[(size_t)M_*512];         // layer1 output concat  [M,512]
__device__ float g_xph[(size_t)T_*B_*16];      // head projections      [T][B][16]
__device__ __nv_bfloat16 g_ah[(size_t)M_*512]; // x hi (bf16)
__device__ __nv_bfloat16 g_al[(size_t)M_*512]; // x lo (bf16 residual)
__device__ __nv_bfloat16 g_wh[(size_t)2*512*512]; // W hi per layer
__device__ __nv_bfloat16 g_wl[(size_t)2*512*512]; // W lo per layer

// ---------------- packed f32x2 FMA ----------------
__device__ __forceinline__ void ffma2(float2 &acc, float2 a, float2 b) {
    asm("fma.rn.f32x2 %0, %1, %2, %0;"
        : "+l"(reinterpret_cast<unsigned long long&>(acc))
        : "l"(reinterpret_cast<unsigned long long&>(a)),
          "l"(reinterpret_cast<unsigned long long&>(b)));
}

__device__ __forceinline__ float ftanh(float x) {
    float ax = fabsf(x);
    float e  = __expf(-2.f * ax);
    float r  = __fdividef(1.f - e, 1.f + e);
    return copysignf(r, x);
}

__device__ __forceinline__ uint32_t s2u(const void* p) {
    uint32_t a;
    asm("{ .reg .u64 t; cvta.to.shared.u64 t, %1; cvt.u32.u64 %0, t; }"
        : "=r"(a) : "l"(p));
    return a;
}
__device__ __forceinline__ void cp_async16(uint32_t smem, const void* gptr) {
    asm volatile("cp.async.cg.shared.global [%0], [%1], 16;"
                 :: "r"(smem), "l"(gptr) : "memory");
}
__device__ __forceinline__ void ldmatrix_x4(uint32_t* r, uint32_t addr) {
    asm volatile("ldmatrix.sync.aligned.m8n8.x4.shared.b16 {%0,%1,%2,%3}, [%4];"
                 : "=r"(r[0]), "=r"(r[1]), "=r"(r[2]), "=r"(r[3]) : "r"(addr));
}
__device__ __forceinline__ void mma16816(float* d, const uint32_t* a,
                                         uint32_t b0, uint32_t b1) {
    asm volatile("mma.sync.aligned.m16n8k16.row.col.f32.bf16.bf16.f32 "
                 "{%0,%1,%2,%3}, {%4,%5,%6,%7}, {%8,%9}, {%0,%1,%2,%3};"
                 : "+f"(d[0]), "+f"(d[1]), "+f"(d[2]), "+f"(d[3])
                 : "r"(a[0]), "r"(a[1]), "r"(a[2]), "r"(a[3]),
                   "r"(b0), "r"(b1));
}

// ---------------- 0a) convert W (both layers) fp32 -> bf16 hi/lo --------------
__global__ void conv_w_kernel(const float* __restrict__ w) {
    int idx = blockIdx.x * 256 + threadIdx.x;     // x4 elems; 2*512*512 total
    float4 v = *(const float4*)(w + (size_t)idx * 4);
    __nv_bfloat16 h0 = __float2bfloat16_rn(v.x), h1 = __float2bfloat16_rn(v.y);
    __nv_bfloat16 h2 = __float2bfloat16_rn(v.z), h3 = __float2bfloat16_rn(v.w);
    __nv_bfloat16 l0 = __float2bfloat16_rn(v.x - __bfloat162float(h0));
    __nv_bfloat16 l1 = __float2bfloat16_rn(v.y - __bfloat162float(h1));
    __nv_bfloat16 l2 = __float2bfloat16_rn(v.z - __bfloat162float(h2));
    __nv_bfloat16 l3 = __float2bfloat16_rn(v.w - __bfloat162float(h3));
    __nv_bfloat162 hp0 = __halves2bfloat162(h0, h1), hp1 = __halves2bfloat162(h2, h3);
    __nv_bfloat162 lp0 = __halves2bfloat162(l0, l1), lp1 = __halves2bfloat162(l2, l3);
    uint2 hu, lu;
    hu.x = *(unsigned*)&hp0; hu.y = *(unsigned*)&hp1;
    lu.x = *(unsigned*)&lp0; lu.y = *(unsigned*)&lp1;
    *(uint2*)(g_wh + (size_t)idx * 4) = hu;
    *(uint2*)(g_wl + (size_t)idx * 4) = lu;
}

// ---------------- 0b) convert x fp32 -> bf16 hi/lo (emb gather, layer 0 only) -
__global__ void conv_x_kernel(const int* __restrict__ tokens,
                              const float* __restrict__ emb) {
    int idx = blockIdx.x * 256 + threadIdx.x;     // float4 id; total M*128
    int m = idx >> 7, c4 = idx & 127;
    int tok = __ldg(&tokens[m]);
    float4 v = *((const float4*)(emb + (size_t)tok * 512) + c4);
    __nv_bfloat16 h0 = __float2bfloat16_rn(v.x), h1 = __float2bfloat16_rn(v.y);
    __nv_bfloat16 h2 = __float2bfloat16_rn(v.z), h3 = __float2bfloat16_rn(v.w);
    __nv_bfloat16 l0 = __float2bfloat16_rn(v.x - __bfloat162float(h0));
    __nv_bfloat16 l1 = __float2bfloat16_rn(v.y - __bfloat162float(h1));
    __nv_bfloat16 l2 = __float2bfloat16_rn(v.z - __bfloat162float(h2));
    __nv_bfloat16 l3 = __float2bfloat16_rn(v.w - __bfloat162float(h3));
    __nv_bfloat162 hp0 = __halves2bfloat162(h0, h1), hp1 = __halves2bfloat162(h2, h3);
    __nv_bfloat162 lp0 = __halves2bfloat162(l0, l1), lp1 = __halves2bfloat162(l2, l3);
    uint2 hu, lu;
    hu.x = *(unsigned*)&hp0; hu.y = *(unsigned*)&hp1;
    lu.x = *(unsigned*)&lp0; lu.y = *(unsigned*)&lp1;
    *(uint2*)(g_ah + (size_t)m * 512 + c4 * 4) = hu;
    *(uint2*)(g_al + (size_t)m * 512 + c4 * 4) = lu;
}

// ---------------- 1) HMMA split-bf16 projection GEMM (proven) ----------------
__global__ __launch_bounds__(256, 2) void mma_gemm_kernel(
    int layer, const float* __restrict__ bih, const float* __restrict__ bhh)
{
    extern __shared__ __align__(128) char smem[];
    char* bufA[2] = { smem,            smem + 32768 };
    char* bufB[2] = { smem + 16384,    smem + 49152 };
    float* bias_s = (float*)(smem + 65536);

    int tid = threadIdx.x, wid = tid >> 5, l = tid & 31;
    int m0 = blockIdx.x * 128, n0 = blockIdx.y * 128;
    int wm = wid & 3, wn = wid >> 2;

    const __nv_bfloat16* whl = g_wh + (size_t)layer * 512 * 512;
    const __nv_bfloat16* wll = g_wl + (size_t)layer * 512 * 512;

    if (tid < 128) bias_s[tid] = bih[n0 + tid] + bhh[n0 + tid];

    int rowA0 = wm * 32 + ((l >> 3) & 1) * 8 + (l & 7);
    int rowB0 = wn * 64 + ((l >> 3) & 1) * 8 + (l & 7);
    int koff  = (l >> 4) * 16;
    int swx   = (l & 7) * 16;

    float d[2][8][4];
#pragma unroll
    for (int mi = 0; mi < 2; mi++)
#pragma unroll
        for (int nj = 0; nj < 8; nj++)
#pragma unroll
            for (int c = 0; c < 4; c++) d[mi][nj][c] = 0.f;

    auto issue_load = [&](int ck, int p) {
        int pass = ck >> 3;
        int k0 = (ck & 7) * 64;
        const __nv_bfloat16* Asrc = (pass == 2) ? g_al : g_ah;
        const __nv_bfloat16* Bsrc = (pass == 1) ? wll : whl;
        uint32_t au = s2u(bufA[p]), bu = s2u(bufB[p]);
#pragma unroll
        for (int s = 0; s < 4; s++) {
            int lin = tid * 4 + s;
            int row = lin >> 3, c = lin & 7;
            uint32_t soff = row * 128 + ((c * 16) ^ ((row & 7) * 16));
            cp_async16(au + soff, Asrc + (size_t)(m0 + row) * 512 + k0 + c * 8);
            cp_async16(bu + soff, Bsrc + (size_t)(n0 + row) * 512 + k0 + c * 8);
        }
        asm volatile("cp.async.commit_group;" ::: "memory");
    };

    issue_load(0, 0);
    asm volatile("cp.async.wait_group 0;" ::: "memory");
    __syncthreads();

    for (int ck = 0; ck < 24; ck++) {
        int p = ck & 1;
        if (ck + 1 < 24) issue_load(ck + 1, p ^ 1);

        uint32_t aBase = s2u(bufA[p]), bBase = s2u(bufB[p]);
#pragma unroll
        for (int q = 0; q < 4; q++) {
            uint32_t low = (uint32_t)((q * 32 + koff) ^ swx);
            uint32_t afr[2][4];
#pragma unroll
            for (int mi = 0; mi < 2; mi++)
                ldmatrix_x4(afr[mi], aBase + (rowA0 + mi * 16) * 128 + low);
            uint32_t bfr[4][4];
#pragma unroll
            for (int ni = 0; ni < 4; ni++)
                ldmatrix_x4(bfr[ni], bBase + (rowB0 + ni * 16) * 128 + low);
#pragma unroll
            for (int mi = 0; mi < 2; mi++)
#pragma unroll
                for (int nj = 0; nj < 8; nj++)
                    mma16816(d[mi][nj], afr[mi],
                             bfr[nj >> 1][nj & 1], bfr[nj >> 1][2 + (nj & 1)]);
        }
        if (ck + 1 < 24) asm volatile("cp.async.wait_group 0;" ::: "memory");
        __syncthreads();
    }

#pragma unroll
    for (int mi = 0; mi < 2; mi++) {
#pragma unroll
        for (int r2 = 0; r2 < 2; r2++) {
            int m = m0 + wm * 32 + mi * 16 + (l >> 2) + r2 * 8;
            int bb = m >> 10, t = m & 1023;
#pragma unroll
            for (int nj = 0; nj < 8; nj++) {
                int nloc = wn * 64 + nj * 8 + (l & 3) * 2;
                int n = n0 + nloc;
                int dd = n >> 8, h = n & 255;
                float2 v;
                v.x = d[mi][nj][r2 * 2    ] + bias_s[nloc    ];
                v.y = d[mi][nj][r2 * 2 + 1] + bias_s[nloc + 1];
                *(float2*)&g_xp[(((size_t)dd * T_ + t) * B_ + bb) * H_ + h] = v;
            }
        }
    }
}

// ---------------- 2) bidirectional RNN recurrence (proven best) --------------
// which_out==0: emit bf16 hi/lo split directly (feeds layer-1 GEMM; no conv).
// which_out==1: emit fp32 to g_x2 (feeds heads).
__global__ __launch_bounds__(512, 1) void rnn_layer_kernel(
    const float* __restrict__ whh, int which_out)
{
    extern __shared__ float sm[];
    float4* Wt4  = (float4*)sm;                  // [WSH4][512] float4
    float*  hbuf = sm + WSH4 * 512 * 4;          // [2][HBUF]

    int tid  = threadIdx.x;
    int j    = tid >> 1;
    int half = tid & 1;
    int d = blockIdx.x & 1;
    int b = blockIdx.x >> 1;
    const float* Wd = whh + (size_t)d * H_ * H_;

    float2 wreg2[WREG2];
    {
        const float2* wrow = (const float2*)(Wd + (size_t)j * H_ + half * 128);
#pragma unroll
        for (int k = 0; k < WREG2; k++) wreg2[k] = wrow[k];
    }
    for (int idx = tid; idx < WSH4 * 512; idx += 512) {
        int kk = idx >> 9;
        int t2 = idx & 511;
        int j2 = t2 >> 1, h2 = t2 & 1;
        Wt4[idx] = *(const float4*)(Wd + (size_t)j2 * H_ + h2 * 128 + 2*WREG2 + 4*kk);
    }
    for (int idx = tid; idx < 2 * HBUF; idx += 512) hbuf[idx] = 0.f;
    __syncthreads();

    const float* xpd = g_xp + (size_t)d * T_ * B_ * H_;
    size_t obase = (size_t)b * T_ * 512 + d * H_ + j;   // element offset

    int t = d ? (T_ - 1) : 0;
    int step = d ? -1 : 1;

    float xv  = xpd[((size_t)t * B_ + b) * H_ + j];
    float xnv = xpd[((size_t)(t + step) * B_ + b) * H_ + j];

    int rb = 0;
    for (int s = 0; s < T_; ++s) {
        float xfut = 0.f;
        if (s + 2 < T_)
            xfut = xpd[((size_t)(t + 2*step) * B_ + b) * H_ + j];

        const float4* h4p = (const float4*)(hbuf + rb * HBUF + half * HSTRIDE);

        float2 a0 = make_float2(0.f,0.f), a1 = a0, a2 = a0, a3 = a0;
#pragma unroll
        for (int q = 0; q < WREG2/2; q++) {
            float4 hv = h4p[q];
            ffma2((q & 1) ? a2 : a0, make_float2(hv.x, hv.y), wreg2[2*q]);
            ffma2((q & 1) ? a3 : a1, make_float2(hv.z, hv.w), wreg2[2*q+1]);
        }
#pragma unroll
        for (int q = 0; q < WSH4; q++) {
            float4 hv = h4p[WREG2/2 + q];
            float4 w  = Wt4[q*512 + tid];
            ffma2((q & 1) ? a2 : a0, make_float2(hv.x, hv.y), make_float2(w.x, w.y));
            ffma2((q & 1) ? a3 : a1, make_float2(hv.z, hv.w), make_float2(w.z, w.w));
        }
        float ssum = (a0.x + a0.y) + (a1.x + a1.y)
                   + (a2.x + a2.y) + (a3.x + a3.y);
        float psum = __shfl_xor_sync(0xffffffffu, ssum, 1);
        float hn = ftanh(ssum + psum + xv);

        int wb = rb ^ 1;
        if (half == 0) {
            hbuf[wb * HBUF + j + ((j >> 7) << 2)] = hn;
        } else {
            size_t off = obase + (size_t)t * 512;
            if (which_out) {
                g_x2[off] = hn;
            } else {
                __nv_bfloat16 hi = __float2bfloat16_rn(hn);
                __nv_bfloat16 lo = __float2bfloat16_rn(hn - __bfloat162float(hi));
                g_ah[off] = hi;
                g_al[off] = lo;
            }
        }

        __syncthreads();
        xv = xnv; xnv = xfut;
        t += step;
        rb = wb;
    }
}

// ---------------- 3) head projections (float4-vectorized) --------------------
__global__ __launch_bounds__(256) void head_xp_kernel(
    const float* __restrict__ wi, const float* __restrict__ bi_ih, const float* __restrict__ bi_hh,
    const float* __restrict__ wf, const float* __restrict__ bf_ih, const float* __restrict__ bf_hh,
    const float* __restrict__ wc, const float* __restrict__ bc_ih, const float* __restrict__ bc_hh)
{
    __shared__ float Ws[13 * 512];
    __shared__ float bs[13];
    int tid = threadIdx.x;
    for (int idx = tid; idx < 13 * 512; idx += 256) {
        int n = idx / 512, k = idx % 512;
        float w;
        if (n < 3)      w = wi[n*512 + k];
        else if (n < 8) w = wf[(n-3)*512 + k];
        else            w = wc[(n-8)*512 + k];
        Ws[idx] = w;
    }
    if (tid < 13) {
        float bv;
        if (tid < 3)      bv = bi_ih[tid]   + bi_hh[tid];
        else if (tid < 8) bv = bf_ih[tid-3] + bf_hh[tid-3];
        else              bv = bc_ih[tid-8] + bc_hh[tid-8];
        bs[tid] = bv;
    }
    __syncthreads();

    int w = tid >> 5, lane = tid & 31;
    int m = blockIdx.x * 8 + w;
    const float4* xr4 = (const float4*)(g_x2 + (size_t)m * 512);

    float acc[13];
#pragma unroll
    for (int n = 0; n < 13; n++) acc[n] = 0.f;

#pragma unroll
    for (int i = 0; i < 4; i++) {
        int k4 = i * 32 + lane;                // float4 index within the row
        float4 xv = xr4[k4];
        xv.x = fmaxf(xv.x, 0.f); xv.y = fmaxf(xv.y, 0.f);
        xv.z = fmaxf(xv.z, 0.f); xv.w = fmaxf(xv.w, 0.f);
#pragma unroll
        for (int n = 0; n < 13; n++) {
            float4 wv = *(const float4*)&Ws[n*512 + k4*4];
            acc[n] += xv.x*wv.x + xv.y*wv.y + xv.z*wv.z + xv.w*wv.w;
        }
    }
#pragma unroll
    for (int n = 0; n < 13; n++) {
#pragma unroll
        for (int off = 16; off; off >>= 1)
            acc[n] += __shfl_xor_sync(0xffffffff, acc[n], off);
    }
    if (lane == 0) {
        int bb = m >> 10, t = m & 1023;
        float* o = g_xph + ((size_t)t * B_ + bb) * 16;
#pragma unroll
        for (int n = 0; n < 13; n++) o[n] = acc[n] + bs[n];
    }
}

// ---------------- 4) head recurrences ----------------
__global__ void head_rnn_kernel(
    const float* __restrict__ wi_hh,
    const float* __restrict__ wf_hh,
    const float* __restrict__ wc_hh,
    float* __restrict__ out)
{
    int hid = blockIdx.x % 3;
    int b   = blockIdx.x / 3;
    int lane = threadIdx.x;
    int C, off;
    size_t outoff;
    const float* Whh;
    if (hid == 0)      { C = 3; off = 0; outoff = 0;                         Whh = wi_hh; }
    else if (hid == 1) { C = 5; off = 3; outoff = (size_t)B_*T_*3;           Whh = wf_hh; }
    else               { C = 5; off = 8; outoff = (size_t)B_*T_*3 + (size_t)B_*T_*5; Whh = wc_hh; }

    float w[5] = {0,0,0,0,0};
    if (lane < C)
        for (int k = 0; k < C; k++) w[k] = Whh[lane*C + k];

    float h = 0.f;
    float* ob = out + outoff + (size_t)b * T_ * C;
    float xv = (lane < C) ? g_xph[((size_t)0 * B_ + b) * 16 + off + lane] : 0.f;
    for (int t = 0; t < T_; t++) {
        float xn = 0.f;
        if (t + 1 < T_ && lane < C)
            xn = g_xph[((size_t)(t+1) * B_ + b) * 16 + off + lane];
        float h0 = __shfl_sync(0xffffffff, h, 0);
        float h1 = __shfl_sync(0xffffffff, h, 1);
        float h2 = __shfl_sync(0xffffffff, h, 2);
        float h3 = __shfl_sync(0xffffffff, h, 3);
        float h4 = __shfl_sync(0xffffffff, h, 4);
        float acc = xv + h0*w[0] + h1*w[1] + h2*w[2] + h3*w[3] + h4*w[4];
        h = ftanh(acc);
        if (lane < C) ob[(size_t)t * C + lane] = h;
        xv = xn;
    }
}

// ---------------- launch ----------------
extern "C" void kernel_launch(void* const* d_in, const int* in_sizes, int n_in,
                              void* d_out, int out_size) {
    const int*   tokens = (const int*)  d_in[0];
    const float* emb    = (const float*)d_in[1];
    const float* w_ih   = (const float*)d_in[2];   // [2][2][256][512]
    const float* w_hh   = (const float*)d_in[3];   // [2][2][256][256]
    const float* b_ih   = (const float*)d_in[4];   // [2][2][256]
    const float* b_hh   = (const float*)d_in[5];
    const float* iw_ih  = (const float*)d_in[6];
    const float* iw_hh  = (const float*)d_in[7];
    const float* ib_ih  = (const float*)d_in[8];
    const float* ib_hh  = (const float*)d_in[9];
    const float* fw_ih  = (const float*)d_in[10];
    const float* fw_hh  = (const float*)d_in[11];
    const float* fb_ih  = (const float*)d_in[12];
    const float* fb_hh  = (const float*)d_in[13];
    const float* cw_ih  = (const float*)d_in[14];
    const float* cw_hh  = (const float*)d_in[15];
    const float* cb_ih  = (const float*)d_in[16];
    const float* cb_hh  = (const float*)d_in[17];
    float* out = (float*)d_out;

    const int rnn_smem = (WSH4 * 512 * 4 + 2 * HBUF) * 4;
    cudaFuncSetAttribute(rnn_layer_kernel,
                         cudaFuncAttributeMaxDynamicSharedMemorySize, rnn_smem);
    const int mma_smem = 65536 + 512;
    cudaFuncSetAttribute(mma_gemm_kernel,
                         cudaFuncAttributeMaxDynamicSharedMemorySize, mma_smem);

    // convert weights once (both layers)
    conv_w_kernel<<<(2*512*512/4)/256, 256>>>(w_ih);

    // layer 0: gather+split x, HMMA GEMM, scan (scan emits bf16 split directly)
    conv_x_kernel<<<(M_*128)/256, 256>>>(tokens, emb);
    mma_gemm_kernel<<<dim3(M_/128, 4), 256, mma_smem>>>(0, b_ih, b_hh);
    rnn_layer_kernel<<<B_ * 2, 512, rnn_smem>>>(w_hh, 0);

    // layer 1: GEMM reads bf16 split written by layer-0 scan
    mma_gemm_kernel<<<dim3(M_/128, 4), 256, mma_smem>>>(1, b_ih + 2*H_, b_hh + 2*H_);
    rnn_layer_kernel<<<B_ * 2, 512, rnn_smem>>>(w_hh + 2*H_*H_, 1);

    // heads
    head_xp_kernel<<<M_/8, 256>>>(iw_ih, ib_ih, ib_hh,
                                  fw_ih, fb_ih, fb_hh,
                                  cw_ih, cb_ih, cb_hh);
    head_rnn_kernel<<<B_ * 3, 32>>>(iw_hh, fw_hh, cw_hh, out);
}

// round 17
// speedup vs baseline: 1.0830x; 1.0830x over previous
#include <cuda_runtime.h>
#include <cuda_bf16.h>
#include <math.h>
#include <stdint.h>

#define B_ 64
#define T_ 1024
#define E_ 512
#define H_ 256
#define M_ (B_*T_)          // 65536

// RNN constants (proven best layout, ~1012us/launch)
#define WREG2 48
#define WSH4  8
#define HSTRIDE 132
#define HBUF   264

// ---------------- scratch (device globals; no allocation allowed) ----------------
__device__ float g_xp[(size_t)2*T_*B_*H_];     // per-layer projections [2][T][B][H]
__device__ float g_x1[(size_t)M_*512];         // layer0 output concat  [M,512]
__device__ float g_x2[(size_t)M_*512];         // layer1 output concat  [M,512]
__device__ float g_xph[(size_t)T_*B_*16];      // head projections      [T][B][16]
__device__ __nv_bfloat16 g_ah[(size_t)M_*512]; // x hi (bf16)
__device__ __nv_bfloat16 g_al[(size_t)M_*512]; // x lo (bf16 residual)
__device__ __nv_bfloat16 g_wh[(size_t)2*512*512]; // W hi per layer
__device__ __nv_bfloat16 g_wl[(size_t)2*512*512]; // W lo per layer

// ---------------- packed f32x2 FMA ----------------
__device__ __forceinline__ void ffma2(float2 &acc, float2 a, float2 b) {
    asm("fma.rn.f32x2 %0, %1, %2, %0;"
        : "+l"(reinterpret_cast<unsigned long long&>(acc))
        : "l"(reinterpret_cast<unsigned long long&>(a)),
          "l"(reinterpret_cast<unsigned long long&>(b)));
}

__device__ __forceinline__ float ftanh(float x) {
    float ax = fabsf(x);
    float e  = __expf(-2.f * ax);
    float r  = __fdividef(1.f - e, 1.f + e);
    return copysignf(r, x);
}

__device__ __forceinline__ uint32_t s2u(const void* p) {
    uint32_t a;
    asm("{ .reg .u64 t; cvta.to.shared.u64 t, %1; cvt.u32.u64 %0, t; }"
        : "=r"(a) : "l"(p));
    return a;
}
__device__ __forceinline__ void cp_async16(uint32_t smem, const void* gptr) {
    asm volatile("cp.async.cg.shared.global [%0], [%1], 16;"
                 :: "r"(smem), "l"(gptr) : "memory");
}
__device__ __forceinline__ void ldmatrix_x4(uint32_t* r, uint32_t addr) {
    asm volatile("ldmatrix.sync.aligned.m8n8.x4.shared.b16 {%0,%1,%2,%3}, [%4];"
                 : "=r"(r[0]), "=r"(r[1]), "=r"(r[2]), "=r"(r[3]) : "r"(addr));
}
__device__ __forceinline__ void mma16816(float* d, const uint32_t* a,
                                         uint32_t b0, uint32_t b1) {
    asm volatile("mma.sync.aligned.m16n8k16.row.col.f32.bf16.bf16.f32 "
                 "{%0,%1,%2,%3}, {%4,%5,%6,%7}, {%8,%9}, {%0,%1,%2,%3};"
                 : "+f"(d[0]), "+f"(d[1]), "+f"(d[2]), "+f"(d[3])
                 : "r"(a[0]), "r"(a[1]), "r"(a[2]), "r"(a[3]),
                   "r"(b0), "r"(b1));
}

// ---------------- 0a) convert W (both layers) fp32 -> bf16 hi/lo --------------
__global__ void conv_w_kernel(const float* __restrict__ w) {
    int idx = blockIdx.x * 256 + threadIdx.x;     // x4 elems; 2*512*512 total
    float4 v = *(const float4*)(w + (size_t)idx * 4);
    __nv_bfloat16 h0 = __float2bfloat16_rn(v.x), h1 = __float2bfloat16_rn(v.y);
    __nv_bfloat16 h2 = __float2bfloat16_rn(v.z), h3 = __float2bfloat16_rn(v.w);
    __nv_bfloat16 l0 = __float2bfloat16_rn(v.x - __bfloat162float(h0));
    __nv_bfloat16 l1 = __float2bfloat16_rn(v.y - __bfloat162float(h1));
    __nv_bfloat16 l2 = __float2bfloat16_rn(v.z - __bfloat162float(h2));
    __nv_bfloat16 l3 = __float2bfloat16_rn(v.w - __bfloat162float(h3));
    __nv_bfloat162 hp0 = __halves2bfloat162(h0, h1), hp1 = __halves2bfloat162(h2, h3);
    __nv_bfloat162 lp0 = __halves2bfloat162(l0, l1), lp1 = __halves2bfloat162(l2, l3);
    uint2 hu, lu;
    hu.x = *(unsigned*)&hp0; hu.y = *(unsigned*)&hp1;
    lu.x = *(unsigned*)&lp0; lu.y = *(unsigned*)&lp1;
    *(uint2*)(g_wh + (size_t)idx * 4) = hu;
    *(uint2*)(g_wl + (size_t)idx * 4) = lu;
}

// ---------------- 0b) convert x fp32 -> bf16 hi/lo (fused emb gather) ---------
__global__ void conv_x_kernel(int which, const int* __restrict__ tokens,
                              const float* __restrict__ emb) {
    int idx = blockIdx.x * 256 + threadIdx.x;     // float4 id; total M*128
    int m = idx >> 7, c4 = idx & 127;
    float4 v;
    if (which) {
        v = *((const float4*)(g_x1 + (size_t)m * 512) + c4);
    } else {
        int tok = __ldg(&tokens[m]);
        v = *((const float4*)(emb + (size_t)tok * 512) + c4);
    }
    __nv_bfloat16 h0 = __float2bfloat16_rn(v.x), h1 = __float2bfloat16_rn(v.y);
    __nv_bfloat16 h2 = __float2bfloat16_rn(v.z), h3 = __float2bfloat16_rn(v.w);
    __nv_bfloat16 l0 = __float2bfloat16_rn(v.x - __bfloat162float(h0));
    __nv_bfloat16 l1 = __float2bfloat16_rn(v.y - __bfloat162float(h1));
    __nv_bfloat16 l2 = __float2bfloat16_rn(v.z - __bfloat162float(h2));
    __nv_bfloat16 l3 = __float2bfloat16_rn(v.w - __bfloat162float(h3));
    __nv_bfloat162 hp0 = __halves2bfloat162(h0, h1), hp1 = __halves2bfloat162(h2, h3);
    __nv_bfloat162 lp0 = __halves2bfloat162(l0, l1), lp1 = __halves2bfloat162(l2, l3);
    uint2 hu, lu;
    hu.x = *(unsigned*)&hp0; hu.y = *(unsigned*)&hp1;
    lu.x = *(unsigned*)&lp0; lu.y = *(unsigned*)&lp1;
    *(uint2*)(g_ah + (size_t)m * 512 + c4 * 4) = hu;
    *(uint2*)(g_al + (size_t)m * 512 + c4 * 4) = lu;
}

// ---------------- 1) HMMA split-bf16 projection GEMM (proven) ----------------
__global__ __launch_bounds__(256, 2) void mma_gemm_kernel(
    int layer, const float* __restrict__ bih, const float* __restrict__ bhh)
{
    extern __shared__ __align__(128) char smem[];
    char* bufA[2] = { smem,            smem + 32768 };
    char* bufB[2] = { smem + 16384,    smem + 49152 };
    float* bias_s = (float*)(smem + 65536);

    int tid = threadIdx.x, wid = tid >> 5, l = tid & 31;
    int m0 = blockIdx.x * 128, n0 = blockIdx.y * 128;
    int wm = wid & 3, wn = wid >> 2;

    const __nv_bfloat16* whl = g_wh + (size_t)layer * 512 * 512;
    const __nv_bfloat16* wll = g_wl + (size_t)layer * 512 * 512;

    if (tid < 128) bias_s[tid] = bih[n0 + tid] + bhh[n0 + tid];

    int rowA0 = wm * 32 + ((l >> 3) & 1) * 8 + (l & 7);
    int rowB0 = wn * 64 + ((l >> 3) & 1) * 8 + (l & 7);
    int koff  = (l >> 4) * 16;
    int swx   = (l & 7) * 16;

    float d[2][8][4];
#pragma unroll
    for (int mi = 0; mi < 2; mi++)
#pragma unroll
        for (int nj = 0; nj < 8; nj++)
#pragma unroll
            for (int c = 0; c < 4; c++) d[mi][nj][c] = 0.f;

    auto issue_load = [&](int ck, int p) {
        int pass = ck >> 3;
        int k0 = (ck & 7) * 64;
        const __nv_bfloat16* Asrc = (pass == 2) ? g_al : g_ah;
        const __nv_bfloat16* Bsrc = (pass == 1) ? wll : whl;
        uint32_t au = s2u(bufA[p]), bu = s2u(bufB[p]);
#pragma unroll
        for (int s = 0; s < 4; s++) {
            int lin = tid * 4 + s;
            int row = lin >> 3, c = lin & 7;
            uint32_t soff = row * 128 + ((c * 16) ^ ((row & 7) * 16));
            cp_async16(au + soff, Asrc + (size_t)(m0 + row) * 512 + k0 + c * 8);
            cp_async16(bu + soff, Bsrc + (size_t)(n0 + row) * 512 + k0 + c * 8);
        }
        asm volatile("cp.async.commit_group;" ::: "memory");
    };

    issue_load(0, 0);
    asm volatile("cp.async.wait_group 0;" ::: "memory");
    __syncthreads();

    for (int ck = 0; ck < 24; ck++) {
        int p = ck & 1;
        if (ck + 1 < 24) issue_load(ck + 1, p ^ 1);

        uint32_t aBase = s2u(bufA[p]), bBase = s2u(bufB[p]);
#pragma unroll
        for (int q = 0; q < 4; q++) {
            uint32_t low = (uint32_t)((q * 32 + koff) ^ swx);
            uint32_t afr[2][4];
#pragma unroll
            for (int mi = 0; mi < 2; mi++)
                ldmatrix_x4(afr[mi], aBase + (rowA0 + mi * 16) * 128 + low);
            uint32_t bfr[4][4];
#pragma unroll
            for (int ni = 0; ni < 4; ni++)
                ldmatrix_x4(bfr[ni], bBase + (rowB0 + ni * 16) * 128 + low);
#pragma unroll
            for (int mi = 0; mi < 2; mi++)
#pragma unroll
                for (int nj = 0; nj < 8; nj++)
                    mma16816(d[mi][nj], afr[mi],
                             bfr[nj >> 1][nj & 1], bfr[nj >> 1][2 + (nj & 1)]);
        }
        if (ck + 1 < 24) asm volatile("cp.async.wait_group 0;" ::: "memory");
        __syncthreads();
    }

#pragma unroll
    for (int mi = 0; mi < 2; mi++) {
#pragma unroll
        for (int r2 = 0; r2 < 2; r2++) {
            int m = m0 + wm * 32 + mi * 16 + (l >> 2) + r2 * 8;
            int bb = m >> 10, t = m & 1023;
#pragma unroll
            for (int nj = 0; nj < 8; nj++) {
                int nloc = wn * 64 + nj * 8 + (l & 3) * 2;
                int n = n0 + nloc;
                int dd = n >> 8, h = n & 255;
                float2 v;
                v.x = d[mi][nj][r2 * 2    ] + bias_s[nloc    ];
                v.y = d[mi][nj][r2 * 2 + 1] + bias_s[nloc + 1];
                *(float2*)&g_xp[(((size_t)dd * T_ + t) * B_ + bb) * H_ + h] = v;
            }
        }
    }
}

// ---------------- 2) bidirectional RNN recurrence (proven best, fp32 out) ----
__global__ __launch_bounds__(512, 1) void rnn_layer_kernel(
    const float* __restrict__ whh, int which_out)
{
    extern __shared__ float sm[];
    float4* Wt4  = (float4*)sm;                  // [WSH4][512] float4
    float*  hbuf = sm + WSH4 * 512 * 4;          // [2][HBUF]
    float*  xnext = which_out ? g_x2 : g_x1;

    int tid  = threadIdx.x;
    int j    = tid >> 1;
    int half = tid & 1;
    int d = blockIdx.x & 1;
    int b = blockIdx.x >> 1;
    const float* Wd = whh + (size_t)d * H_ * H_;

    float2 wreg2[WREG2];
    {
        const float2* wrow = (const float2*)(Wd + (size_t)j * H_ + half * 128);
#pragma unroll
        for (int k = 0; k < WREG2; k++) wreg2[k] = wrow[k];
    }
    for (int idx = tid; idx < WSH4 * 512; idx += 512) {
        int kk = idx >> 9;
        int t2 = idx & 511;
        int j2 = t2 >> 1, h2 = t2 & 1;
        Wt4[idx] = *(const float4*)(Wd + (size_t)j2 * H_ + h2 * 128 + 2*WREG2 + 4*kk);
    }
    for (int idx = tid; idx < 2 * HBUF; idx += 512) hbuf[idx] = 0.f;
    __syncthreads();

    const float* xpd = g_xp + (size_t)d * T_ * B_ * H_;
    float* outp = xnext + (size_t)b * T_ * 512 + d * H_ + j;

    int t = d ? (T_ - 1) : 0;
    int step = d ? -1 : 1;

    float xv  = xpd[((size_t)t * B_ + b) * H_ + j];
    float xnv = xpd[((size_t)(t + step) * B_ + b) * H_ + j];

    int rb = 0;
    for (int s = 0; s < T_; ++s) {
        float xfut = 0.f;
        if (s + 2 < T_)
            xfut = xpd[((size_t)(t + 2*step) * B_ + b) * H_ + j];

        const float4* h4p = (const float4*)(hbuf + rb * HBUF + half * HSTRIDE);

        float2 a0 = make_float2(0.f,0.f), a1 = a0, a2 = a0, a3 = a0;
#pragma unroll
        for (int q = 0; q < WREG2/2; q++) {
            float4 hv = h4p[q];
            ffma2((q & 1) ? a2 : a0, make_float2(hv.x, hv.y), wreg2[2*q]);
            ffma2((q & 1) ? a3 : a1, make_float2(hv.z, hv.w), wreg2[2*q+1]);
        }
#pragma unroll
        for (int q = 0; q < WSH4; q++) {
            float4 hv = h4p[WREG2/2 + q];
            float4 w  = Wt4[q*512 + tid];
            ffma2((q & 1) ? a2 : a0, make_float2(hv.x, hv.y), make_float2(w.x, w.y));
            ffma2((q & 1) ? a3 : a1, make_float2(hv.z, hv.w), make_float2(w.z, w.w));
        }
        float ssum = (a0.x + a0.y) + (a1.x + a1.y)
                   + (a2.x + a2.y) + (a3.x + a3.y);
        float psum = __shfl_xor_sync(0xffffffffu, ssum, 1);
        float hn = ftanh(ssum + psum + xv);

        int wb = rb ^ 1;
        if (half == 0) hbuf[wb * HBUF + j + ((j >> 7) << 2)] = hn;
        else           outp[(size_t)t * 512] = hn;

        __syncthreads();
        xv = xnv; xnv = xfut;
        t += step;
        rb = wb;
    }
}

// ---------------- 3) head projections (float4-vectorized) --------------------
__global__ __launch_bounds__(256) void head_xp_kernel(
    const float* __restrict__ wi, const float* __restrict__ bi_ih, const float* __restrict__ bi_hh,
    const float* __restrict__ wf, const float* __restrict__ bf_ih, const float* __restrict__ bf_hh,
    const float* __restrict__ wc, const float* __restrict__ bc_ih, const float* __restrict__ bc_hh)
{
    __shared__ float Ws[13 * 512];
    __shared__ float bs[13];
    int tid = threadIdx.x;
    for (int idx = tid; idx < 13 * 512; idx += 256) {
        int n = idx / 512, k = idx % 512;
        float w;
        if (n < 3)      w = wi[n*512 + k];
        else if (n < 8) w = wf[(n-3)*512 + k];
        else            w = wc[(n-8)*512 + k];
        Ws[idx] = w;
    }
    if (tid < 13) {
        float bv;
        if (tid < 3)      bv = bi_ih[tid]   + bi_hh[tid];
        else if (tid < 8) bv = bf_ih[tid-3] + bf_hh[tid-3];
        else              bv = bc_ih[tid-8] + bc_hh[tid-8];
        bs[tid] = bv;
    }
    __syncthreads();

    int w = tid >> 5, lane = tid & 31;
    int m = blockIdx.x * 8 + w;
    const float4* xr4 = (const float4*)(g_x2 + (size_t)m * 512);

    float acc[13];
#pragma unroll
    for (int n = 0; n < 13; n++) acc[n] = 0.f;

#pragma unroll
    for (int i = 0; i < 4; i++) {
        int k4 = i * 32 + lane;                // float4 index within the row
        float4 xv = xr4[k4];
        xv.x = fmaxf(xv.x, 0.f); xv.y = fmaxf(xv.y, 0.f);
        xv.z = fmaxf(xv.z, 0.f); xv.w = fmaxf(xv.w, 0.f);
#pragma unroll
        for (int n = 0; n < 13; n++) {
            float4 wv = *(const float4*)&Ws[n*512 + k4*4];
            acc[n] += xv.x*wv.x + xv.y*wv.y + xv.z*wv.z + xv.w*wv.w;
        }
    }
#pragma unroll
    for (int n = 0; n < 13; n++) {
#pragma unroll
        for (int off = 16; off; off >>= 1)
            acc[n] += __shfl_xor_sync(0xffffffff, acc[n], off);
    }
    if (lane == 0) {
        int bb = m >> 10, t = m & 1023;
        float* o = g_xph + ((size_t)t * B_ + bb) * 16;
#pragma unroll
        for (int n = 0; n < 13; n++) o[n] = acc[n] + bs[n];
    }
}

// ---------------- 4) head recurrences ----------------
__global__ void head_rnn_kernel(
    const float* __restrict__ wi_hh,
    const float* __restrict__ wf_hh,
    const float* __restrict__ wc_hh,
    float* __restrict__ out)
{
    int hid = blockIdx.x % 3;
    int b   = blockIdx.x / 3;
    int lane = threadIdx.x;
    int C, off;
    size_t outoff;
    const float* Whh;
    if (hid == 0)      { C = 3; off = 0; outoff = 0;                         Whh = wi_hh; }
    else if (hid == 1) { C = 5; off = 3; outoff = (size_t)B_*T_*3;           Whh = wf_hh; }
    else               { C = 5; off = 8; outoff = (size_t)B_*T_*3 + (size_t)B_*T_*5; Whh = wc_hh; }

    float w[5] = {0,0,0,0,0};
    if (lane < C)
        for (int k = 0; k < C; k++) w[k] = Whh[lane*C + k];

    float h = 0.f;
    float* ob = out + outoff + (size_t)b * T_ * C;
    float xv = (lane < C) ? g_xph[((size_t)0 * B_ + b) * 16 + off + lane] : 0.f;
    for (int t = 0; t < T_; t++) {
        float xn = 0.f;
        if (t + 1 < T_ && lane < C)
            xn = g_xph[((size_t)(t+1) * B_ + b) * 16 + off + lane];
        float h0 = __shfl_sync(0xffffffff, h, 0);
        float h1 = __shfl_sync(0xffffffff, h, 1);
        float h2 = __shfl_sync(0xffffffff, h, 2);
        float h3 = __shfl_sync(0xffffffff, h, 3);
        float h4 = __shfl_sync(0xffffffff, h, 4);
        float acc = xv + h0*w[0] + h1*w[1] + h2*w[2] + h3*w[3] + h4*w[4];
        h = ftanh(acc);
        if (lane < C) ob[(size_t)t * C + lane] = h;
        xv = xn;
    }
}

// ---------------- launch ----------------
extern "C" void kernel_launch(void* const* d_in, const int* in_sizes, int n_in,
                              void* d_out, int out_size) {
    const int*   tokens = (const int*)  d_in[0];
    const float* emb    = (const float*)d_in[1];
    const float* w_ih   = (const float*)d_in[2];   // [2][2][256][512]
    const float* w_hh   = (const float*)d_in[3];   // [2][2][256][256]
    const float* b_ih   = (const float*)d_in[4];   // [2][2][256]
    const float* b_hh   = (const float*)d_in[5];
    const float* iw_ih  = (const float*)d_in[6];
    const float* iw_hh  = (const float*)d_in[7];
    const float* ib_ih  = (const float*)d_in[8];
    const float* ib_hh  = (const float*)d_in[9];
    const float* fw_ih  = (const float*)d_in[10];
    const float* fw_hh  = (const float*)d_in[11];
    const float* fb_ih  = (const float*)d_in[12];
    const float* fb_hh  = (const float*)d_in[13];
    const float* cw_ih  = (const float*)d_in[14];
    const float* cw_hh  = (const float*)d_in[15];
    const float* cb_ih  = (const float*)d_in[16];
    const float* cb_hh  = (const float*)d_in[17];
    float* out = (float*)d_out;

    const int rnn_smem = (WSH4 * 512 * 4 + 2 * HBUF) * 4;
    cudaFuncSetAttribute(rnn_layer_kernel,
                         cudaFuncAttributeMaxDynamicSharedMemorySize, rnn_smem);
    const int mma_smem = 65536 + 512;
    cudaFuncSetAttribute(mma_gemm_kernel,
                         cudaFuncAttributeMaxDynamicSharedMemorySize, mma_smem);

    // convert weights once (both layers)
    conv_w_kernel<<<(2*512*512/4)/256, 256>>>(w_ih);

    // layer 0: gather+split x, HMMA GEMM, scan
    conv_x_kernel<<<(M_*128)/256, 256>>>(0, tokens, emb);
    mma_gemm_kernel<<<dim3(M_/128, 4), 256, mma_smem>>>(0, b_ih, b_hh);
    rnn_layer_kernel<<<B_ * 2, 512, rnn_smem>>>(w_hh, 0);

    // layer 1
    conv_x_kernel<<<(M_*128)/256, 256>>>(1, tokens, emb);
    mma_gemm_kernel<<<dim3(M_/128, 4), 256, mma_smem>>>(1, b_ih + 2*H_, b_hh + 2*H_);
    rnn_layer_kernel<<<B_ * 2, 512, rnn_smem>>>(w_hh + 2*H_*H_, 1);

    // heads
    head_xp_kernel<<<M_/8, 256>>>(iw_ih, ib_ih, ib_hh,
                                  fw_ih, fb_ih, fb_hh,
                                  cw_ih, cb_ih, cb_hh);
    head_rnn_kernel<<<B_ * 3, 32>>>(iw_hh, fw_hh, cw_hh, out);
}